// round 1
// baseline (speedup 1.0000x reference)
#include <cuda_runtime.h>
#include <cstdint>

// ---------------- scratch (no mallocs allowed) ----------------
__device__ float g_partial[16 * 4 * 2 * 4096];          // [cs][b][oc][hw]  2 MB
__device__ float g_sampled[16777216ULL];                 // [b][c][hw] 4*1024*4096, 67 MB

// =====================================================================
// Kernel 1: offset conv partials.
// Conv2d(concat(refer,sup): 2048ch -> 2, k=3, pad=1), split 16 ways over
// channels. Block: (cs, b*4+htile). 256 thr = 64 cols x 4 row-strips of 4.
// =====================================================================
__global__ __launch_bounds__(256) void conv_kernel(
    const float* __restrict__ refer, const float* __restrict__ sup,
    const float* __restrict__ w_off)
{
    __shared__ float tile[18 * 66];
    __shared__ float wsh[18];

    int cs = blockIdx.x;            // 0..15 channel split
    int b  = blockIdx.y >> 2;       // 0..3
    int ht = blockIdx.y & 3;        // 0..3
    int r0 = ht * 16;
    int c0 = cs * 128;              // concat-channel base

    const float* src = (c0 < 1024)
        ? refer + (size_t)b * 1024 * 4096 + (size_t)c0 * 4096
        : sup   + (size_t)b * 1024 * 4096 + (size_t)(c0 - 1024) * 4096;

    int tid = threadIdx.x;
    int x   = tid & 63;
    int py0 = (tid >> 6) * 4;       // 0,4,8,12

    float acc0[4] = {0.f, 0.f, 0.f, 0.f};
    float acc1[4] = {0.f, 0.f, 0.f, 0.f};

    for (int c = 0; c < 128; ++c) {
        const float* chan = src + (size_t)c * 4096;
        __syncthreads();
        // load 18x66 padded tile (rows r0-1..r0+16, cols -1..64), zeros outside
        for (int i = tid; i < 18 * 66; i += 256) {
            int row = i / 66;
            int col = i - row * 66;
            int gr = r0 + row - 1;
            int gc = col - 1;
            float v = 0.f;
            if (gr >= 0 && gr < 64 && gc >= 0 && gc < 64) v = chan[gr * 64 + gc];
            tile[i] = v;
        }
        if (tid < 18) {
            int oc = tid / 9, t9 = tid - oc * 9;
            wsh[tid] = w_off[(size_t)oc * 2048 * 9 + (size_t)(c0 + c) * 9 + t9];
        }
        __syncthreads();

        float w0[9], w1[9];
        #pragma unroll
        for (int j = 0; j < 9; ++j) { w0[j] = wsh[j]; w1[j] = wsh[9 + j]; }

        #pragma unroll
        for (int kx = 0; kx < 3; ++kx) {
            float v[6];
            #pragma unroll
            for (int j = 0; j < 6; ++j) v[j] = tile[(py0 + j) * 66 + x + kx];
            #pragma unroll
            for (int py = 0; py < 4; ++py) {
                #pragma unroll
                for (int ky = 0; ky < 3; ++ky) {
                    acc0[py] += w0[ky * 3 + kx] * v[py + ky];
                    acc1[py] += w1[ky * 3 + kx] * v[py + ky];
                }
            }
        }
    }

    #pragma unroll
    for (int py = 0; py < 4; ++py) {
        int pix = (r0 + py0 + py) * 64 + x;
        g_partial[(((size_t)cs * 4 + b) * 2 + 0) * 4096 + pix] = acc0[py];
        g_partial[(((size_t)cs * 4 + b) * 2 + 1) * 4096 + pix] = acc1[py];
    }
}

// =====================================================================
// Kernel 2: reduce offset partials, compute bilinear corner indices /
// weights (zero pad outside), gather-sample sup_feat for a 256-channel
// quarter. Grid: (16 pixel strips, 4 batch, 4 channel quarters).
// =====================================================================
__global__ __launch_bounds__(256) void sample_kernel(
    const float* __restrict__ sup, const float* __restrict__ b_off)
{
    int pix = blockIdx.x * 256 + threadIdx.x;
    int b   = blockIdx.y;
    int cq  = blockIdx.z;

    float o0 = b_off[0], o1 = b_off[1];
    #pragma unroll
    for (int cs = 0; cs < 16; ++cs) {
        o0 += g_partial[((cs * 4 + b) * 2 + 0) * 4096 + pix];
        o1 += g_partial[((cs * 4 + b) * 2 + 1) * 4096 + pix];
    }

    int h = pix >> 6, w = pix & 63;
    float py = o0 + (float)h;      // offset ch0 = dy
    float px = o1 + (float)w;      // offset ch1 = dx
    float y0f = floorf(py), x0f = floorf(px);
    float wy = py - y0f, wx = px - x0f;
    int y0 = (int)y0f, x0 = (int)x0f;
    int y1 = y0 + 1,  x1 = x0 + 1;

    float vy0 = (y0 >= 0 && y0 < 64) ? 1.f : 0.f;
    float vy1 = (y1 >= 0 && y1 < 64) ? 1.f : 0.f;
    float vx0 = (x0 >= 0 && x0 < 64) ? 1.f : 0.f;
    float vx1 = (x1 >= 0 && x1 < 64) ? 1.f : 0.f;
    int cy0 = min(max(y0, 0), 63), cy1 = min(max(y1, 0), 63);
    int cx0 = min(max(x0, 0), 63), cx1 = min(max(x1, 0), 63);
    int i00 = cy0 * 64 + cx0, i01 = cy0 * 64 + cx1;
    int i10 = cy1 * 64 + cx0, i11 = cy1 * 64 + cx1;
    float w00 = (1.f - wy) * (1.f - wx) * vy0 * vx0;
    float w01 = (1.f - wy) * wx         * vy0 * vx1;
    float w10 = wy * (1.f - wx)         * vy1 * vx0;
    float w11 = wy * wx                 * vy1 * vx1;

    const float* base = sup       + ((size_t)b * 1024 + cq * 256) * 4096;
    float*       out  = g_sampled + ((size_t)b * 1024 + cq * 256) * 4096 + pix;

    #pragma unroll 4
    for (int c = 0; c < 256; ++c) {
        const float* p = base + (size_t)c * 4096;
        out[(size_t)c * 4096] =
            w00 * p[i00] + w01 * p[i01] + w10 * p[i10] + w11 * p[i11];
    }
}

// =====================================================================
// Kernel 3: tf32 tensor-core GEMM.
// out[b] (2048x4096) = w_def (2048x1024) @ sampled[b] (1024x4096)
// Block tile 128x128x16, 8 warps (2x4), warp tile 64x32, mma m16n8k8.
// cp.async double buffering. rna-rounded tf32.
// =====================================================================
__device__ __forceinline__ uint32_t f2tf(float x) {
    uint32_t r;
    asm("cvt.rna.tf32.f32 %0, %1;" : "=r"(r) : "f"(x));
    return r;
}

__device__ __forceinline__ void mma_tf32(float* c, const uint32_t* a, const uint32_t* bb) {
    asm volatile(
        "mma.sync.aligned.m16n8k8.row.col.f32.tf32.tf32.f32 "
        "{%0,%1,%2,%3},{%4,%5,%6,%7},{%8,%9},{%0,%1,%2,%3};"
        : "+f"(c[0]), "+f"(c[1]), "+f"(c[2]), "+f"(c[3])
        : "r"(a[0]), "r"(a[1]), "r"(a[2]), "r"(a[3]), "r"(bb[0]), "r"(bb[1]));
}

__device__ __forceinline__ void cpa16(float* smem, const float* g) {
    uint32_t s = (uint32_t)__cvta_generic_to_shared(smem);
    asm volatile("cp.async.cg.shared.global [%0], [%1], 16;\n" :: "r"(s), "l"(g) : "memory");
}

__global__ __launch_bounds__(256) void gemm_kernel(
    const float* __restrict__ Wd, float* __restrict__ Out)
{
    __shared__ float As[2][128 * 20];   // stride 20 floats (16B aligned, conflict-free frags)
    __shared__ float Bs[2][16 * 136];   // stride 136 floats (16B aligned, conflict-free frags)

    int nt = blockIdx.x, mt = blockIdx.y, b = blockIdx.z;
    const float* Bg = g_sampled + (size_t)b * 1024 * 4096 + nt * 128;
    float*       Og = Out       + (size_t)b * 2048 * 4096;
    const float* Ag = Wd + (size_t)(mt * 128) * 1024;

    int tid = threadIdx.x;
    int arow0 = tid >> 2,          ac4 = (tid & 3) * 4;
    int arow1 = (tid + 256) >> 2;
    int brow0 = tid >> 5,          bc4 = (tid & 31) * 4;
    int brow1 = (tid + 256) >> 5;

#define LOAD_TILE(bufi, k0) do {                                             \
    cpa16(&As[bufi][arow0 * 20 + ac4], Ag + (size_t)arow0 * 1024 + (k0) + ac4); \
    cpa16(&As[bufi][arow1 * 20 + ac4], Ag + (size_t)arow1 * 1024 + (k0) + ac4); \
    cpa16(&Bs[bufi][brow0 * 136 + bc4], Bg + (size_t)((k0) + brow0) * 4096 + bc4); \
    cpa16(&Bs[bufi][brow1 * 136 + bc4], Bg + (size_t)((k0) + brow1) * 4096 + bc4); \
    asm volatile("cp.async.commit_group;\n" ::: "memory");                   \
} while (0)

    int warp = tid >> 5, lane = tid & 31;
    int wm = warp >> 2, wn = warp & 3;          // 2 x 4 warp grid
    int g  = lane >> 2, tg = lane & 3;

    float acc[4][4][4];
    #pragma unroll
    for (int im = 0; im < 4; ++im)
        #pragma unroll
        for (int in = 0; in < 4; ++in)
            #pragma unroll
            for (int r = 0; r < 4; ++r) acc[im][in][r] = 0.f;

    LOAD_TILE(0, 0);

    for (int kt = 0; kt < 64; ++kt) {
        int cur = kt & 1;
        if (kt < 63) {
            LOAD_TILE(cur ^ 1, (kt + 1) * 16);
            asm volatile("cp.async.wait_group 1;\n" ::: "memory");
        } else {
            asm volatile("cp.async.wait_group 0;\n" ::: "memory");
        }
        __syncthreads();

        const float* Asb = As[cur];
        const float* Bsb = Bs[cur];
        #pragma unroll
        for (int kk = 0; kk < 16; kk += 8) {
            uint32_t bfr[4][2];
            #pragma unroll
            for (int in = 0; in < 4; ++in) {
                const float* bp = &Bsb[(kk + tg) * 136 + wn * 32 + in * 8 + g];
                bfr[in][0] = f2tf(bp[0]);
                bfr[in][1] = f2tf(bp[544]);       // +4 rows * 136
            }
            #pragma unroll
            for (int im = 0; im < 4; ++im) {
                const float* ap = &Asb[(wm * 64 + im * 16 + g) * 20 + kk + tg];
                uint32_t afr[4];
                afr[0] = f2tf(ap[0]);
                afr[1] = f2tf(ap[160]);           // +8 rows * 20
                afr[2] = f2tf(ap[4]);
                afr[3] = f2tf(ap[164]);
                #pragma unroll
                for (int in = 0; in < 4; ++in) mma_tf32(acc[im][in], afr, bfr[in]);
            }
        }
        __syncthreads();
    }

    // epilogue
    #pragma unroll
    for (int im = 0; im < 4; ++im) {
        #pragma unroll
        for (int in = 0; in < 4; ++in) {
            int row = mt * 128 + wm * 64 + im * 16 + g;
            int col = nt * 128 + wn * 32 + in * 8 + tg * 2;
            float2 v0 = make_float2(acc[im][in][0], acc[im][in][1]);
            float2 v1 = make_float2(acc[im][in][2], acc[im][in][3]);
            *(float2*)&Og[(size_t)row * 4096 + col]       = v0;
            *(float2*)&Og[(size_t)(row + 8) * 4096 + col] = v1;
        }
    }
#undef LOAD_TILE
}

// =====================================================================
extern "C" void kernel_launch(void* const* d_in, const int* in_sizes, int n_in,
                              void* d_out, int out_size)
{
    const float* refer = (const float*)d_in[0];
    const float* sup   = (const float*)d_in[1];
    const float* w_off = (const float*)d_in[2];
    const float* b_off = (const float*)d_in[3];
    const float* w_def = (const float*)d_in[4];
    float* out = (float*)d_out;

    conv_kernel  <<<dim3(16, 16),    256>>>(refer, sup, w_off);
    sample_kernel<<<dim3(16, 4, 4),  256>>>(sup, b_off);
    gemm_kernel  <<<dim3(32, 16, 4), 256>>>(w_def, out);
}

// round 2
// speedup vs baseline: 1.3761x; 1.3761x over previous
#include <cuda_runtime.h>
#include <cstdint>

// ---------------- scratch (no mallocs allowed) ----------------
__device__ float g_S[16 * 4 * 18 * 4096];     // [split][b][tap][pix]   18.9 MB
__device__ float g_offset[4 * 2 * 4096];      // [b][oc][pix]
__device__ float g_sampled[4 * 1024 * 4096];  // [b][c][pix]  tf32-rounded, 67 MB
__device__ float g_wdef[2048 * 1024];         // tf32-rounded w_def, 8 MB

__device__ __forceinline__ uint32_t f2tf(float x) {
    uint32_t r;
    asm("cvt.rna.tf32.f32 %0, %1;" : "=r"(r) : "f"(x));
    return r;
}

#define FMA2(d, a, b, c) \
    asm("fma.rn.f32x2 %0, %1, %2, %3;" : "=l"(d) : "l"(a), "l"(b), "l"(c))

// =====================================================================
// Kernel 1a: tap-decomposed offset conv, stage 1 (channel reduction).
// S[split][b][tap][pix] = sum_{c in split} w[oc,c,ky,kx] * in[b,c,pix]
// Pure streaming GEMV, packed f32x2 FMA, no per-channel syncs.
// Grid (8 pixel blocks, 4 batch, 16 channel splits), 256 thr, 2 px/thr.
// =====================================================================
__global__ __launch_bounds__(256) void conv_taps_kernel(
    const float* __restrict__ refer, const float* __restrict__ sup,
    const float* __restrict__ w_off)
{
    __shared__ float2 wsh[128 * 18];   // per-channel weights, duplicated {w,w}

    int split = blockIdx.z;
    int b     = blockIdx.y;
    int c0    = split * 128;           // concat-channel base
    int tid   = threadIdx.x;

    for (int i = tid; i < 128 * 18; i += 256) {
        int c = i / 18, tap = i - c * 18;
        int oc = tap / 9, t9 = tap - oc * 9;
        float w = w_off[((size_t)oc * 2048 + c0 + c) * 9 + t9];
        wsh[i] = make_float2(w, w);
    }
    __syncthreads();

    const float* src = (c0 < 1024)
        ? refer + ((size_t)b * 1024 + c0) * 4096
        : sup   + ((size_t)b * 1024 + (c0 - 1024)) * 4096;

    int px = (blockIdx.x * 256 + tid) * 2;

    unsigned long long acc[18];
    #pragma unroll
    for (int t = 0; t < 18; ++t) acc[t] = 0ull;   // packed {0.f, 0.f}

    #pragma unroll 2
    for (int c = 0; c < 128; ++c) {
        unsigned long long v =
            *(const unsigned long long*)(src + (size_t)c * 4096 + px);
        const unsigned long long* wp =
            (const unsigned long long*)&wsh[c * 18];
        #pragma unroll
        for (int t = 0; t < 18; ++t) FMA2(acc[t], wp[t], v, acc[t]);
    }

    float* outb = g_S + (((size_t)split * 4 + b) * 18) * 4096 + px;
    #pragma unroll
    for (int t = 0; t < 18; ++t)
        *(unsigned long long*)(outb + (size_t)t * 4096) = acc[t];
}

// =====================================================================
// Kernel 1b: combine shifted taps + reduce 16 channel splits -> offsets.
// out[b,oc,y,x] = b_off[oc] + sum_{ky,kx,split} S[...][y+ky-1, x+kx-1]
// =====================================================================
__global__ __launch_bounds__(256) void offset_combine_kernel(
    const float* __restrict__ b_off)
{
    int pix = blockIdx.x * 256 + threadIdx.x;
    int b   = blockIdx.y;
    int y = pix >> 6, x = pix & 63;

    #pragma unroll
    for (int oc = 0; oc < 2; ++oc) {
        float acc = b_off[oc];
        #pragma unroll
        for (int ky = 0; ky < 3; ++ky) {
            int yy = y + ky - 1;
            bool vy = (yy >= 0) && (yy < 64);
            #pragma unroll
            for (int kx = 0; kx < 3; ++kx) {
                int xx = x + kx - 1;
                if (vy && xx >= 0 && xx < 64) {
                    int sp = yy * 64 + xx;
                    int tap = oc * 9 + ky * 3 + kx;
                    #pragma unroll 4
                    for (int s = 0; s < 16; ++s)
                        acc += g_S[(((size_t)s * 4 + b) * 18 + tap) * 4096 + sp];
                }
            }
        }
        g_offset[(b * 2 + oc) * 4096 + pix] = acc;
    }
}

// =====================================================================
// Kernel 2: bilinear gather-sample of sup_feat; stores tf32-rounded.
// Grid: (16 pixel strips, 4 batch, 4 channel quarters).
// =====================================================================
__global__ __launch_bounds__(256) void sample_kernel(
    const float* __restrict__ sup)
{
    int pix = blockIdx.x * 256 + threadIdx.x;
    int b   = blockIdx.y;
    int cq  = blockIdx.z;

    float o0 = g_offset[(b * 2 + 0) * 4096 + pix];
    float o1 = g_offset[(b * 2 + 1) * 4096 + pix];

    int h = pix >> 6, w = pix & 63;
    float py = o0 + (float)h;      // offset ch0 = dy
    float px = o1 + (float)w;      // offset ch1 = dx
    float y0f = floorf(py), x0f = floorf(px);
    float wy = py - y0f, wx = px - x0f;
    int y0 = (int)y0f, x0 = (int)x0f;
    int y1 = y0 + 1,  x1 = x0 + 1;

    float vy0 = (y0 >= 0 && y0 < 64) ? 1.f : 0.f;
    float vy1 = (y1 >= 0 && y1 < 64) ? 1.f : 0.f;
    float vx0 = (x0 >= 0 && x0 < 64) ? 1.f : 0.f;
    float vx1 = (x1 >= 0 && x1 < 64) ? 1.f : 0.f;
    int cy0 = min(max(y0, 0), 63), cy1 = min(max(y1, 0), 63);
    int cx0 = min(max(x0, 0), 63), cx1 = min(max(x1, 0), 63);
    int i00 = cy0 * 64 + cx0, i01 = cy0 * 64 + cx1;
    int i10 = cy1 * 64 + cx0, i11 = cy1 * 64 + cx1;
    float w00 = (1.f - wy) * (1.f - wx) * vy0 * vx0;
    float w01 = (1.f - wy) * wx         * vy0 * vx1;
    float w10 = wy * (1.f - wx)         * vy1 * vx0;
    float w11 = wy * wx                 * vy1 * vx1;

    const float* base = sup       + ((size_t)b * 1024 + cq * 256) * 4096;
    float*       out  = g_sampled + ((size_t)b * 1024 + cq * 256) * 4096 + pix;

    #pragma unroll 4
    for (int c = 0; c < 256; ++c) {
        const float* p = base + (size_t)c * 4096;
        float r = w00 * p[i00] + w01 * p[i01] + w10 * p[i10] + w11 * p[i11];
        out[(size_t)c * 4096] = __uint_as_float(f2tf(r));   // pre-round to tf32
    }
}

// =====================================================================
// Kernel 2b: pre-round w_def to tf32 (removes cvt from GEMM inner loop).
// =====================================================================
__global__ __launch_bounds__(256) void round_wdef_kernel(
    const float* __restrict__ w)
{
    int i = blockIdx.x * 256 + threadIdx.x;
    g_wdef[i] = __uint_as_float(f2tf(w[i]));
}

// =====================================================================
// Kernel 3: tf32 tensor-core GEMM.
// out[b] (2048x4096) = g_wdef (2048x1024) @ g_sampled[b] (1024x4096)
// Block tile 128x128x16, 8 warps (2x4), warp tile 64x32, mma m16n8k8.
// 3-stage cp.async pipeline, ONE barrier per k-tile, no cvt inside.
// =====================================================================
__device__ __forceinline__ void mma_tf32(float* c, const uint32_t* a, const uint32_t* bb) {
    asm volatile(
        "mma.sync.aligned.m16n8k8.row.col.f32.tf32.tf32.f32 "
        "{%0,%1,%2,%3},{%4,%5,%6,%7},{%8,%9},{%0,%1,%2,%3};"
        : "+f"(c[0]), "+f"(c[1]), "+f"(c[2]), "+f"(c[3])
        : "r"(a[0]), "r"(a[1]), "r"(a[2]), "r"(a[3]), "r"(bb[0]), "r"(bb[1]));
}

__device__ __forceinline__ void cpa16(float* smem, const float* g) {
    uint32_t s = (uint32_t)__cvta_generic_to_shared(smem);
    asm volatile("cp.async.cg.shared.global [%0], [%1], 16;\n" :: "r"(s), "l"(g) : "memory");
}

static constexpr int AS_STRIDE = 20;               // floats/row, conflict-free frags
static constexpr int BS_STRIDE = 136;
static constexpr int AS_BUF = 128 * AS_STRIDE;     // 2560 floats
static constexpr int BS_BUF = 16 * BS_STRIDE;      // 2176 floats
static constexpr int GEMM_SMEM = (3 * AS_BUF + 3 * BS_BUF) * 4;  // 56832 B

__global__ __launch_bounds__(256) void gemm_kernel(float* __restrict__ Out)
{
    extern __shared__ float smem[];
    float* As = smem;                    // 3 stages
    float* Bs = smem + 3 * AS_BUF;

    int nt = blockIdx.x, mt = blockIdx.y, b = blockIdx.z;
    const float* Bg = g_sampled + (size_t)b * 1024 * 4096 + nt * 128;
    const float* Ag = g_wdef + (size_t)(mt * 128) * 1024;
    float*       Og = Out + (size_t)b * 2048 * 4096;

    int tid = threadIdx.x;
    int arow0 = tid >> 2,          ac4 = (tid & 3) * 4;
    int arow1 = (tid + 256) >> 2;
    int brow0 = tid >> 5,          bc4 = (tid & 31) * 4;
    int brow1 = (tid + 256) >> 5;

#define LOAD_TILE(bufi, k0) do {                                                      \
    float* Ad = As + (bufi) * AS_BUF;                                                 \
    float* Bd = Bs + (bufi) * BS_BUF;                                                 \
    cpa16(Ad + arow0 * AS_STRIDE + ac4, Ag + (size_t)arow0 * 1024 + (k0) + ac4);      \
    cpa16(Ad + arow1 * AS_STRIDE + ac4, Ag + (size_t)arow1 * 1024 + (k0) + ac4);      \
    cpa16(Bd + brow0 * BS_STRIDE + bc4, Bg + (size_t)((k0) + brow0) * 4096 + bc4);    \
    cpa16(Bd + brow1 * BS_STRIDE + bc4, Bg + (size_t)((k0) + brow1) * 4096 + bc4);    \
    asm volatile("cp.async.commit_group;\n" ::: "memory");                            \
} while (0)

    int warp = tid >> 5, lane = tid & 31;
    int wm = warp >> 2, wn = warp & 3;          // 2 x 4 warp grid
    int g  = lane >> 2, tg = lane & 3;

    float acc[4][4][4];
    #pragma unroll
    for (int im = 0; im < 4; ++im)
        #pragma unroll
        for (int in = 0; in < 4; ++in)
            #pragma unroll
            for (int r = 0; r < 4; ++r) acc[im][in][r] = 0.f;

    LOAD_TILE(0, 0);
    LOAD_TILE(1, 16);

    for (int kt = 0; kt < 64; ++kt) {
        int buf = kt % 3;
        if (kt < 63)
            asm volatile("cp.async.wait_group 1;\n" ::: "memory");
        else
            asm volatile("cp.async.wait_group 0;\n" ::: "memory");
        __syncthreads();
        if (kt < 62) LOAD_TILE((kt + 2) % 3, (kt + 2) * 16);

        const float* Asb = As + buf * AS_BUF;
        const float* Bsb = Bs + buf * BS_BUF;
        #pragma unroll
        for (int kk = 0; kk < 16; kk += 8) {
            uint32_t bfr[4][2];
            #pragma unroll
            for (int in = 0; in < 4; ++in) {
                const float* bp = &Bsb[(kk + tg) * BS_STRIDE + wn * 32 + in * 8 + g];
                bfr[in][0] = __float_as_uint(bp[0]);
                bfr[in][1] = __float_as_uint(bp[4 * BS_STRIDE]);
            }
            #pragma unroll
            for (int im = 0; im < 4; ++im) {
                const float* ap = &Asb[(wm * 64 + im * 16 + g) * AS_STRIDE + kk + tg];
                uint32_t afr[4];
                afr[0] = __float_as_uint(ap[0]);
                afr[1] = __float_as_uint(ap[8 * AS_STRIDE]);
                afr[2] = __float_as_uint(ap[4]);
                afr[3] = __float_as_uint(ap[8 * AS_STRIDE + 4]);
                #pragma unroll
                for (int in = 0; in < 4; ++in) mma_tf32(acc[im][in], afr, bfr[in]);
            }
        }
    }

    // epilogue
    #pragma unroll
    for (int im = 0; im < 4; ++im) {
        #pragma unroll
        for (int in = 0; in < 4; ++in) {
            int row = mt * 128 + wm * 64 + im * 16 + g;
            int col = nt * 128 + wn * 32 + in * 8 + tg * 2;
            float2 v0 = make_float2(acc[im][in][0], acc[im][in][1]);
            float2 v1 = make_float2(acc[im][in][2], acc[im][in][3]);
            *(float2*)&Og[(size_t)row * 4096 + col]       = v0;
            *(float2*)&Og[(size_t)(row + 8) * 4096 + col] = v1;
        }
    }
#undef LOAD_TILE
}

// =====================================================================
extern "C" void kernel_launch(void* const* d_in, const int* in_sizes, int n_in,
                              void* d_out, int out_size)
{
    const float* refer = (const float*)d_in[0];
    const float* sup   = (const float*)d_in[1];
    const float* w_off = (const float*)d_in[2];
    const float* b_off = (const float*)d_in[3];
    const float* w_def = (const float*)d_in[4];
    float* out = (float*)d_out;

    conv_taps_kernel    <<<dim3(8, 4, 16),  256>>>(refer, sup, w_off);
    round_wdef_kernel   <<<8192,            256>>>(w_def);
    offset_combine_kernel<<<dim3(16, 4),    256>>>(b_off);
    sample_kernel       <<<dim3(16, 4, 4),  256>>>(sup);

    cudaFuncSetAttribute(gemm_kernel, cudaFuncAttributeMaxDynamicSharedMemorySize,
                         GEMM_SMEM);
    gemm_kernel<<<dim3(32, 16, 4), 256, GEMM_SMEM>>>(out);
}

// round 4
// speedup vs baseline: 1.7927x; 1.3028x over previous
#include <cuda_runtime.h>
#include <cstdint>

// ---------------- scratch (no mallocs allowed) ----------------
__device__ float g_S[16 * 4 * 18 * 4096];       // conv tap partials, 18.9 MB
__device__ float g_offset[4 * 2 * 4096];        // [b][oc][pix]
// B in mma-fragment order: [b][nt32][k8:128][n8:16][lane:32][2]  (67 MB)
__device__ float g_Bfrag[4ULL * 32 * 128 * 1024];
// A in mma-fragment order: [mt16][k8:128][m16:8][lane:32][4]     (8 MB)
__device__ float g_Afrag[16ULL * 128 * 1024];

__device__ __forceinline__ uint32_t f2tf(float x) {
    uint32_t r;
    asm("cvt.rna.tf32.f32 %0, %1;" : "=r"(r) : "f"(x));
    return r;
}

#define FMA2(d, a, b, c) \
    asm("fma.rn.f32x2 %0, %1, %2, %3;" : "=l"(d) : "l"(a), "l"(b), "l"(c))

// =====================================================================
// Kernel 1a: tap-decomposed offset conv, stage 1 (channel reduction).
// =====================================================================
__global__ __launch_bounds__(256) void conv_taps_kernel(
    const float* __restrict__ refer, const float* __restrict__ sup,
    const float* __restrict__ w_off)
{
    __shared__ float2 wsh[128 * 18];

    int split = blockIdx.z;
    int b     = blockIdx.y;
    int c0    = split * 128;
    int tid   = threadIdx.x;

    for (int i = tid; i < 128 * 18; i += 256) {
        int c = i / 18, tap = i - c * 18;
        int oc = tap / 9, t9 = tap - oc * 9;
        float w = w_off[((size_t)oc * 2048 + c0 + c) * 9 + t9];
        wsh[i] = make_float2(w, w);
    }
    __syncthreads();

    const float* src = (c0 < 1024)
        ? refer + ((size_t)b * 1024 + c0) * 4096
        : sup   + ((size_t)b * 1024 + (c0 - 1024)) * 4096;

    int px = (blockIdx.x * 256 + tid) * 2;

    unsigned long long acc[18];
    #pragma unroll
    for (int t = 0; t < 18; ++t) acc[t] = 0ull;

    #pragma unroll 2
    for (int c = 0; c < 128; ++c) {
        unsigned long long v =
            *(const unsigned long long*)(src + (size_t)c * 4096 + px);
        const unsigned long long* wp = (const unsigned long long*)&wsh[c * 18];
        #pragma unroll
        for (int t = 0; t < 18; ++t) FMA2(acc[t], wp[t], v, acc[t]);
    }

    float* outb = g_S + (((size_t)split * 4 + b) * 18) * 4096 + px;
    #pragma unroll
    for (int t = 0; t < 18; ++t)
        *(unsigned long long*)(outb + (size_t)t * 4096) = acc[t];
}

// =====================================================================
// Kernel 1b: combine shifted taps + reduce splits -> offsets.
// =====================================================================
__global__ __launch_bounds__(256) void offset_combine_kernel(
    const float* __restrict__ b_off)
{
    int pix = blockIdx.x * 256 + threadIdx.x;
    int b   = blockIdx.y;
    int y = pix >> 6, x = pix & 63;

    #pragma unroll
    for (int oc = 0; oc < 2; ++oc) {
        float acc = b_off[oc];
        #pragma unroll
        for (int ky = 0; ky < 3; ++ky) {
            int yy = y + ky - 1;
            bool vy = (yy >= 0) && (yy < 64);
            #pragma unroll
            for (int kx = 0; kx < 3; ++kx) {
                int xx = x + kx - 1;
                if (vy && xx >= 0 && xx < 64) {
                    int sp = yy * 64 + xx;
                    int tap = oc * 9 + ky * 3 + kx;
                    #pragma unroll 4
                    for (int s = 0; s < 16; ++s)
                        acc += g_S[(((size_t)s * 4 + b) * 18 + tap) * 4096 + sp];
                }
            }
        }
        g_offset[(b * 2 + oc) * 4096 + pix] = acc;
    }
}

// =====================================================================
// Kernel 2: bilinear gather-sample -> B in mma-fragment order, tf32.
// For k-offset j in a k8 group, col g: lane = g*4 + (j&3), reg = j>>2.
// Float pos within lane-block = g*8 + (j&3)*2 + (j>>2). Two float4
// stores per (pixel, k8): fully 32B coalesced.
// =====================================================================
__global__ __launch_bounds__(256) void sample_kernel(
    const float* __restrict__ sup)
{
    int pix = blockIdx.x * 256 + threadIdx.x;
    int b   = blockIdx.y;
    int cq  = blockIdx.z;

    float o0 = g_offset[(b * 2 + 0) * 4096 + pix];
    float o1 = g_offset[(b * 2 + 1) * 4096 + pix];

    int h = pix >> 6, w = pix & 63;
    float py = o0 + (float)h;
    float px = o1 + (float)w;
    float y0f = floorf(py), x0f = floorf(px);
    float wy = py - y0f, wx = px - x0f;
    int y0 = (int)y0f, x0 = (int)x0f;
    int y1 = y0 + 1,  x1 = x0 + 1;

    float vy0 = (y0 >= 0 && y0 < 64) ? 1.f : 0.f;
    float vy1 = (y1 >= 0 && y1 < 64) ? 1.f : 0.f;
    float vx0 = (x0 >= 0 && x0 < 64) ? 1.f : 0.f;
    float vx1 = (x1 >= 0 && x1 < 64) ? 1.f : 0.f;
    int cy0 = min(max(y0, 0), 63), cy1 = min(max(y1, 0), 63);
    int cx0 = min(max(x0, 0), 63), cx1 = min(max(x1, 0), 63);
    int i00 = cy0 * 64 + cx0, i01 = cy0 * 64 + cx1;
    int i10 = cy1 * 64 + cx0, i11 = cy1 * 64 + cx1;
    float w00 = (1.f - wy) * (1.f - wx) * vy0 * vx0;
    float w01 = (1.f - wy) * wx         * vy0 * vx1;
    float w10 = wy * (1.f - wx)         * vy1 * vx0;
    float w11 = wy * wx                 * vy1 * vx1;

    const float* base = sup + ((size_t)b * 1024 + cq * 256) * 4096;

    int nt = pix >> 7, n8 = (pix >> 3) & 15, g = pix & 7;
    float* outb = g_Bfrag + (((size_t)b * 32 + nt) * 128) * 1024;

    for (int k8 = 0; k8 < 32; ++k8) {
        int k8g = cq * 32 + k8;
        float buf[8];
        #pragma unroll
        for (int j = 0; j < 8; ++j) {
            const float* p = base + (size_t)(k8 * 8 + j) * 4096;
            float r = w00 * p[i00] + w01 * p[i01] + w10 * p[i10] + w11 * p[i11];
            buf[(j & 3) * 2 + (j >> 2)] = __uint_as_float(f2tf(r));
        }
        float* dst = outb + (size_t)k8g * 1024 + n8 * 64 + g * 8;
        *(float4*)dst       = *(float4*)buf;
        *(float4*)(dst + 4) = *(float4*)(buf + 4);
    }
}

// =====================================================================
// Kernel 2b: w_def -> tf32, mma A-fragment order.
// a0=A[g][tg], a1=A[g+8][tg], a2=A[g][tg+4], a3=A[g+8][tg+4];
// lane = g*4+tg; reg = (row>=8) + 2*(k>=4).
// =====================================================================
__global__ __launch_bounds__(256) void wdef_frag_kernel(
    const float* __restrict__ wd)
{
    int t = blockIdx.x * 256 + threadIdx.x;   // 2048*128 threads: (o, k8)
    int o = t >> 7, k8 = t & 127;
    int mt = o >> 7, mrow = o & 127;
    int m16 = mrow >> 4, r16 = mrow & 15;
    int g = r16 & 7, hi = r16 >> 3;

    const float* src = wd + (size_t)o * 1024 + k8 * 8;
    float* dstc = g_Afrag + ((size_t)mt * 128 + k8) * 1024 + m16 * 128;

    #pragma unroll
    for (int j = 0; j < 8; ++j) {
        int tg = j & 3, chi = j >> 2;
        dstc[(g * 4 + tg) * 4 + hi + 2 * chi] =
            __uint_as_float(f2tf(src[j]));
    }
}

// =====================================================================
// Kernel 3: tf32 mma.sync GEMM with fragment-order operands.
// CTA tile 128x128, warp tile 64x32 (8 warps 2x4). 4-stage cp.async
// pipeline (16KB/stage: A 8KB + B 8KB per k16). Inner loop: pure
// vector LDS + mma, no cvt, no permutes.
// =====================================================================
__device__ __forceinline__ void mma_tf32(float* c, const uint32_t* a, const uint32_t* bb) {
    asm volatile(
        "mma.sync.aligned.m16n8k8.row.col.f32.tf32.tf32.f32 "
        "{%0,%1,%2,%3},{%4,%5,%6,%7},{%8,%9},{%0,%1,%2,%3};"
        : "+f"(c[0]), "+f"(c[1]), "+f"(c[2]), "+f"(c[3])
        : "r"(a[0]), "r"(a[1]), "r"(a[2]), "r"(a[3]), "r"(bb[0]), "r"(bb[1]));
}

__device__ __forceinline__ void cpa16(float* smem, const float* g) {
    uint32_t s = (uint32_t)__cvta_generic_to_shared(smem);
    asm volatile("cp.async.cg.shared.global [%0], [%1], 16;\n" :: "r"(s), "l"(g) : "memory");
}

static constexpr int STAGE_FLOATS = 4096;          // A 2048 + B 2048
static constexpr int GEMM_SMEM = 4 * STAGE_FLOATS * 4;   // 64 KB

__global__ __launch_bounds__(256, 2) void gemm_kernel(float* __restrict__ Out)
{
    extern __shared__ float sm[];

    int tid = threadIdx.x;
    int warp = tid >> 5, lane = tid & 31;
    int wm = warp >> 2, wn = warp & 3;
    int nt = blockIdx.x, mt = blockIdx.y, b = blockIdx.z;

    const float* Ag = g_Afrag + (size_t)mt * 128 * 1024;
    const float* Bg = g_Bfrag + ((size_t)b * 32 + nt) * 128 * 1024;

#define LOAD(s, kt) do {                                                   \
    float* dA = sm + (s) * STAGE_FLOATS;                                   \
    float* dB = dA + 2048;                                                 \
    const float* ga = Ag + (size_t)(kt) * 2048;                            \
    const float* gb = Bg + (size_t)(kt) * 2048;                            \
    cpa16(dA + tid * 4,         ga + tid * 4);                             \
    cpa16(dA + (tid + 256) * 4, ga + (tid + 256) * 4);                     \
    cpa16(dB + tid * 4,         gb + tid * 4);                             \
    cpa16(dB + (tid + 256) * 4, gb + (tid + 256) * 4);                     \
    asm volatile("cp.async.commit_group;\n" ::: "memory");                 \
} while (0)

    float acc[4][4][4];
    #pragma unroll
    for (int im = 0; im < 4; ++im)
        #pragma unroll
        for (int in = 0; in < 4; ++in)
            #pragma unroll
            for (int r = 0; r < 4; ++r) acc[im][in][r] = 0.f;

    LOAD(0, 0);
    LOAD(1, 1);
    LOAD(2, 2);

    for (int kt = 0; kt < 64; ++kt) {
        int s = kt & 3;
        asm volatile("cp.async.wait_group 2;\n" ::: "memory");
        __syncthreads();
        if (kt + 3 < 64)
            LOAD((kt + 3) & 3, kt + 3);
        else
            asm volatile("cp.async.commit_group;\n" ::: "memory");  // keep group count uniform

        const float* sA = sm + s * STAGE_FLOATS;
        const float* sB = sA + 2048;

        #pragma unroll
        for (int kk = 0; kk < 2; ++kk) {
            uint32_t afr[4][4];
            uint32_t bfr[4][2];
            #pragma unroll
            for (int im = 0; im < 4; ++im) {
                float4 v = *(const float4*)&sA[(kk * 8 + wm * 4 + im) * 128 + lane * 4];
                afr[im][0] = __float_as_uint(v.x);
                afr[im][1] = __float_as_uint(v.y);
                afr[im][2] = __float_as_uint(v.z);
                afr[im][3] = __float_as_uint(v.w);
            }
            #pragma unroll
            for (int in = 0; in < 4; ++in) {
                float2 v = *(const float2*)&sB[(kk * 16 + wn * 4 + in) * 64 + lane * 2];
                bfr[in][0] = __float_as_uint(v.x);
                bfr[in][1] = __float_as_uint(v.y);
            }
            #pragma unroll
            for (int im = 0; im < 4; ++im)
                #pragma unroll
                for (int in = 0; in < 4; ++in)
                    mma_tf32(acc[im][in], afr[im], bfr[in]);
        }
    }

    // epilogue: C frag c0=C[g][2tg], c1=C[g][2tg+1], c2/c3 at +8 rows
    float* Og = Out + (size_t)b * 2048 * 4096;
    int g = lane >> 2, tg = lane & 3;
    #pragma unroll
    for (int im = 0; im < 4; ++im) {
        #pragma unroll
        for (int in = 0; in < 4; ++in) {
            int row = mt * 128 + wm * 64 + im * 16 + g;
            int col = nt * 128 + wn * 32 + in * 8 + tg * 2;
            float2 v0 = make_float2(acc[im][in][0], acc[im][in][1]);
            float2 v1 = make_float2(acc[im][in][2], acc[im][in][3]);
            *(float2*)&Og[(size_t)row * 4096 + col]       = v0;
            *(float2*)&Og[(size_t)(row + 8) * 4096 + col] = v1;
        }
    }
#undef LOAD
}

// =====================================================================
extern "C" void kernel_launch(void* const* d_in, const int* in_sizes, int n_in,
                              void* d_out, int out_size)
{
    const float* refer = (const float*)d_in[0];
    const float* sup   = (const float*)d_in[1];
    const float* w_off = (const float*)d_in[2];
    const float* b_off = (const float*)d_in[3];
    const float* w_def = (const float*)d_in[4];
    float* out = (float*)d_out;

    conv_taps_kernel     <<<dim3(8, 4, 16), 256>>>(refer, sup, w_off);
    wdef_frag_kernel     <<<1024,           256>>>(w_def);
    offset_combine_kernel<<<dim3(16, 4),    256>>>(b_off);
    sample_kernel        <<<dim3(16, 4, 4), 256>>>(sup);

    cudaFuncSetAttribute(gemm_kernel, cudaFuncAttributeMaxDynamicSharedMemorySize,
                         GEMM_SMEM);
    gemm_kernel<<<dim3(32, 16, 4), 256, GEMM_SMEM>>>(out);
}